// round 3
// baseline (speedup 1.0000x reference)
#include <cuda_runtime.h>
#include <cuda_bf16.h>
#include <stdint.h>

// ---------------------------------------------------------------------------
// Problem constants
// ---------------------------------------------------------------------------
#define BATCH     16
#define N_PROP    2000
#define N_PAD     2048
#define MAX_GT    100
#define IMG_H     160
#define IMG_W     160
#define T_ROIS    200
#define NUM_POS   66
#define NUM_NEG   134
#define MH        28
#define MW        28

// output layout (float32, tuple order: rois, class_ids, deltas, masks)
#define OFF_ROIS  0
#define OFF_CLS   (BATCH * T_ROIS * 4)                 // 12800
#define OFF_DEL   (OFF_CLS + BATCH * T_ROIS)           // 16000
#define OFF_MASK  (OFF_DEL + BATCH * T_ROIS * 4)       // 28800

// XLA rewrites x / const -> x * (1/const); replicate for bit-exactness.
#define RECIP_033  (1.0f / 0.33f)
#define RECIP_27   (1.0f / 27.0f)

// ---------------------------------------------------------------------------
// Scratch (no allocations allowed -> __device__ globals)
// ---------------------------------------------------------------------------
__device__ unsigned long long g_poskey[BATCH * N_PAD];
__device__ unsigned long long g_negkey[BATCH * N_PAD];
__device__ int   g_argmax[BATCH * N_PROP];
__device__ float g_mbox[BATCH * NUM_POS * 4];
__device__ int   g_mg[BATCH * NUM_POS];
__device__ int   g_mv[BATCH * NUM_POS];

// ---------------------------------------------------------------------------
// JAX threefry2x32 (partitionable mode semantics)
// ---------------------------------------------------------------------------
__host__ __device__ __forceinline__ void tf2x32(unsigned k0, unsigned k1,
                                                unsigned x0, unsigned x1,
                                                unsigned &o0, unsigned &o1) {
    unsigned ks0 = k0, ks1 = k1, ks2 = k0 ^ k1 ^ 0x1BD11BDAu;
    x0 += ks0; x1 += ks1;
#define TFR(r) { x0 += x1; x1 = (x1 << (r)) | (x1 >> (32 - (r))); x1 ^= x0; }
    TFR(13) TFR(15) TFR(26) TFR(6)  x0 += ks1; x1 += ks2 + 1u;
    TFR(17) TFR(29) TFR(16) TFR(24) x0 += ks2; x1 += ks0 + 2u;
    TFR(13) TFR(15) TFR(26) TFR(6)  x0 += ks0; x1 += ks1 + 3u;
    TFR(17) TFR(29) TFR(16) TFR(24) x0 += ks1; x1 += ks2 + 4u;
    TFR(13) TFR(15) TFR(26) TFR(6)  x0 += ks2; x1 += ks0 + 5u;
#undef TFR
    o0 = x0; o1 = x1;
}

// jax.random.uniform float path: bitcast((bits>>9)|1.0f_bits) - 1.0f
__device__ __forceinline__ float u01_from_bits(unsigned bits) {
    return __uint_as_float((bits >> 9) | 0x3f800000u) - 1.0f;
}

// order-preserving float->uint32 map + index tiebreak (lower index first
// when sorted DESCENDING on the composite key)
__device__ __forceinline__ unsigned long long pack_key(float f, int idx) {
    unsigned u = __float_as_uint(f);
    u = (u & 0x80000000u) ? ~u : (u | 0x80000000u);
    return (((unsigned long long)u) << 32) | (unsigned)(~idx);
}

struct KeySet {
    unsigned kp0[BATCH], kp1[BATCH], kn0[BATCH], kn1[BATCH];
};

// ---------------------------------------------------------------------------
// Kernel 1: per-proposal IoU max/argmax, random scores, packed sort keys
// ---------------------------------------------------------------------------
__global__ void k_score(const float* __restrict__ proposals,
                        const int*   __restrict__ gt_cls,
                        const float* __restrict__ gt_boxes,
                        KeySet keys) {
    const int b = blockIdx.y;
    const int n = blockIdx.x * blockDim.x + threadIdx.x;

    __shared__ float sg[MAX_GT][4];
    __shared__ int   sgv[MAX_GT];
    for (int i = threadIdx.x; i < MAX_GT; i += blockDim.x) {
        const float* gb = gt_boxes + (b * MAX_GT + i) * 4;
        sg[i][0] = gb[0]; sg[i][1] = gb[1]; sg[i][2] = gb[2]; sg[i][3] = gb[3];
        sgv[i] = gt_cls[b * MAX_GT + i] > 0;
    }
    __syncthreads();

    if (n >= N_PROP) {
        if (n < N_PAD) {   // padding entries: key 0 sorts below everything real
            g_poskey[b * N_PAD + n] = 0ull;
            g_negkey[b * N_PAD + n] = 0ull;
        }
        return;
    }

    const float* p = proposals + (b * N_PROP + n) * 4;
    const float p0 = p[0], p1 = p[1], p2 = p[2], p3 = p[3];
    const bool vp = (p0 != 0.f) || (p1 != 0.f) || (p2 != 0.f) || (p3 != 0.f);
    const float a1 = __fmul_rn(__fsub_rn(p2, p0), __fsub_rn(p3, p1));

    float best = -1.0f;
    int bestg = 0;
    #pragma unroll 4
    for (int g = 0; g < MAX_GT; ++g) {
        float ov = -1.0f;
        if (sgv[g]) {
            const float q0 = sg[g][0], q1 = sg[g][1], q2 = sg[g][2], q3 = sg[g][3];
            const float yA = fmaxf(p0, q0), xA = fmaxf(p1, q1);
            const float yB = fminf(p2, q2), xB = fminf(p3, q3);
            const float ih = fmaxf(__fsub_rn(yB, yA), 0.f);
            const float iw = fmaxf(__fsub_rn(xB, xA), 0.f);
            const float inter = __fmul_rn(ih, iw);
            const float a2 = __fmul_rn(__fsub_rn(q2, q0), __fsub_rn(q3, q1));
            const float uni = __fsub_rn(__fadd_rn(a1, a2), inter);
            ov = __fdiv_rn(inter, fmaxf(uni, 1e-10f));
        }
        if (ov > best) { best = ov; bestg = g; }   // first-max = jnp.argmax
    }
    g_argmax[b * N_PROP + n] = bestg;

    const bool pos = (best >= 0.5f) && vp;
    const bool neg = (best <  0.5f) && vp;

    unsigned o0, o1;
    tf2x32(keys.kp0[b], keys.kp1[b], 0u, (unsigned)n, o0, o1);
    const float up = u01_from_bits(o0 ^ o1);
    tf2x32(keys.kn0[b], keys.kn1[b], 0u, (unsigned)n, o0, o1);
    const float un = u01_from_bits(o0 ^ o1);

    g_poskey[b * N_PAD + n] = pack_key(pos ? up : -1.0f, n);
    g_negkey[b * N_PAD + n] = pack_key(neg ? un : -1.0f, n);
}

// ---------------------------------------------------------------------------
// Bitonic sort (descending), 2048 elements, blockDim.x = 1024
// ---------------------------------------------------------------------------
__device__ void bitonic_desc(unsigned long long* s, int tid) {
    for (unsigned k = 2; k <= N_PAD; k <<= 1) {
        for (unsigned j = k >> 1; j > 0; j >>= 1) {
            __syncthreads();
            for (unsigned i = tid; i < N_PAD; i += 1024) {
                const unsigned ixj = i ^ j;
                if (ixj > i) {
                    const unsigned long long a = s[i], c = s[ixj];
                    const bool swp = ((i & k) == 0) ? (a < c) : (a > c);
                    if (swp) { s[i] = c; s[ixj] = a; }
                }
            }
        }
    }
    __syncthreads();
}

// ---------------------------------------------------------------------------
// Kernel 2: per image: sort pos, sort neg, emit rois/class/deltas + mask info
// ---------------------------------------------------------------------------
__global__ void __launch_bounds__(1024)
k_select(const float* __restrict__ proposals,
         const int*   __restrict__ gt_cls,
         const float* __restrict__ gt_boxes,
         const float* __restrict__ std4,
         float* __restrict__ out) {
    const int b = blockIdx.x;
    const int tid = threadIdx.x;

    __shared__ unsigned long long s[N_PAD];
    __shared__ int sp_idx[NUM_POS];
    __shared__ unsigned char sp_v[NUM_POS];
    __shared__ int s_need;

    // -------- positives --------
    for (int i = tid; i < N_PAD; i += 1024) s[i] = g_poskey[b * N_PAD + i];
    bitonic_desc(s, tid);
    if (tid < NUM_POS) {
        const unsigned long long k = s[tid];
        sp_idx[tid] = (int)(~(unsigned)k);
        sp_v[tid] = ((unsigned)(k >> 32)) > 0x80000000u;   // score > 0.0
    }
    __syncthreads();
    if (tid == 0) {
        int P = 0;
        for (int i = 0; i < NUM_POS; ++i) P += sp_v[i];
        // XLA: P/0.33 lowered to P * fl(1/0.33f); then f32->s32 truncation
        const int t = (int)__fmul_rn((float)P, RECIP_033);
        int need = t - P;
        need = need < 0 ? 0 : (need > NUM_NEG ? NUM_NEG : need);
        s_need = need;
    }
    __syncthreads();

    // -------- negatives --------
    for (int i = tid; i < N_PAD; i += 1024) s[i] = g_negkey[b * N_PAD + i];
    bitonic_desc(s, tid);

    // -------- outputs --------
    float* o_rois = out + OFF_ROIS;
    float* o_cls  = out + OFF_CLS;
    float* o_del  = out + OFF_DEL;

    if (tid < NUM_POS) {
        const int slot = tid;
        const int n = sp_idx[slot];
        const int v = sp_v[slot];
        const float vf = v ? 1.0f : 0.0f;

        const float* p = proposals + (b * N_PROP + n) * 4;
        const float b0 = p[0], b1 = p[1], b2 = p[2], b3 = p[3];
        const int g = g_argmax[b * N_PROP + n];

        float q0, q1, q2, q3;
        if (v) {
            const float* gb = gt_boxes + (b * MAX_GT + g) * 4;
            q0 = gb[0]; q1 = gb[1]; q2 = gb[2]; q3 = gb[3];
        } else {
            q0 = b0; q1 = b1; q2 = b2; q3 = b3;
        }

        const float h  = __fsub_rn(b2, b0), w  = __fsub_rn(b3, b1);
        const float cy = __fadd_rn(b0, __fmul_rn(0.5f, h));
        const float cx = __fadd_rn(b1, __fmul_rn(0.5f, w));
        const float gh = __fsub_rn(q2, q0), gw = __fsub_rn(q3, q1);
        const float gcy = __fadd_rn(q0, __fmul_rn(0.5f, gh));
        const float gcx = __fadd_rn(q1, __fmul_rn(0.5f, gw));

        float d0 = __fdiv_rn(__fsub_rn(gcy, cy), h);
        float d1 = __fdiv_rn(__fsub_rn(gcx, cx), w);
        float d2 = logf(__fdiv_rn(gh, h));
        float d3 = logf(__fdiv_rn(gw, w));
        d0 = __fmul_rn(__fdiv_rn(d0, std4[0]), vf);
        d1 = __fmul_rn(__fdiv_rn(d1, std4[1]), vf);
        d2 = __fmul_rn(__fdiv_rn(d2, std4[2]), vf);
        d3 = __fmul_rn(__fdiv_rn(d3, std4[3]), vf);

        float* r = o_rois + (b * T_ROIS + slot) * 4;
        r[0] = __fmul_rn(b0, vf); r[1] = __fmul_rn(b1, vf);
        r[2] = __fmul_rn(b2, vf); r[3] = __fmul_rn(b3, vf);

        o_cls[b * T_ROIS + slot] = v ? (float)gt_cls[b * MAX_GT + g] : 0.0f;

        float* d = o_del + (b * T_ROIS + slot) * 4;
        d[0] = d0; d[1] = d1; d[2] = d2; d[3] = d3;

        const int mi = b * NUM_POS + slot;
        g_mbox[mi * 4 + 0] = b0; g_mbox[mi * 4 + 1] = b1;
        g_mbox[mi * 4 + 2] = b2; g_mbox[mi * 4 + 3] = b3;
        g_mg[mi] = g;
        g_mv[mi] = v;
    } else if (tid < T_ROIS) {
        const int j = tid - NUM_POS;
        const unsigned long long k = s[j];
        const int n = (int)(~(unsigned)k);
        const int v = (((unsigned)(k >> 32)) > 0x80000000u) && (j < s_need);
        const float vf = v ? 1.0f : 0.0f;
        const float* p = proposals + (b * N_PROP + n) * 4;

        float* r = o_rois + (b * T_ROIS + tid) * 4;
        r[0] = __fmul_rn(p[0], vf); r[1] = __fmul_rn(p[1], vf);
        r[2] = __fmul_rn(p[2], vf); r[3] = __fmul_rn(p[3], vf);
        o_cls[b * T_ROIS + tid] = 0.0f;
        float* d = o_del + (b * T_ROIS + tid) * 4;
        d[0] = 0.f; d[1] = 0.f; d[2] = 0.f; d[3] = 0.f;
    }
}

// ---------------------------------------------------------------------------
// Kernel 3: mask crop_and_resize (tf bilinear semantics) + zero fill
// ---------------------------------------------------------------------------
__global__ void k_mask(const float* __restrict__ masks_in,
                       float* __restrict__ out) {
    const int slot = blockIdx.x;
    const int b    = blockIdx.y;
    float* dst = out + OFF_MASK + (size_t)(b * T_ROIS + slot) * (MH * MW);

    int v = 0, g = 0;
    float y1 = 0.f, x1 = 0.f, y2 = 0.f, x2 = 0.f;
    if (slot < NUM_POS) {
        const int mi = b * NUM_POS + slot;
        v = g_mv[mi];
        g = g_mg[mi];
        y1 = g_mbox[mi * 4 + 0]; x1 = g_mbox[mi * 4 + 1];
        y2 = g_mbox[mi * 4 + 2]; x2 = g_mbox[mi * 4 + 3];
    }
    if (!v) {
        for (int i = threadIdx.x; i < MH * MW; i += blockDim.x) dst[i] = 0.0f;
        return;
    }

    const size_t base = (size_t)b * IMG_H * IMG_W * MAX_GT + g;
    const float dy = __fsub_rn(y2, y1);
    const float dx = __fsub_rn(x2, x1);

    for (int i = threadIdx.x; i < MH * MW; i += blockDim.x) {
        const int r = i / MW, c = i % MW;
        // XLA: arange/(MH-1) lowered to arange * fl(1/27)
        const float ty = __fmul_rn((float)r, RECIP_27);
        const float tx = __fmul_rn((float)c, RECIP_27);
        const float ys = __fmul_rn(__fadd_rn(y1, __fmul_rn(ty, dy)), (float)(IMG_H - 1));
        const float xs = __fmul_rn(__fadd_rn(x1, __fmul_rn(tx, dx)), (float)(IMG_W - 1));
        const float y0f = floorf(ys), x0f = floorf(xs);
        const float fy = __fsub_rn(ys, y0f), fx = __fsub_rn(xs, x0f);
        int y0 = (int)y0f; y0 = y0 < 0 ? 0 : (y0 > IMG_H - 1 ? IMG_H - 1 : y0);
        int x0 = (int)x0f; x0 = x0 < 0 ? 0 : (x0 > IMG_W - 1 ? IMG_W - 1 : x0);
        const int y1i = min(y0 + 1, IMG_H - 1);
        const int x1i = min(x0 + 1, IMG_W - 1);

        const float m00 = masks_in[base + ((size_t)y0  * IMG_W + x0 ) * MAX_GT];
        const float m01 = masks_in[base + ((size_t)y0  * IMG_W + x1i) * MAX_GT];
        const float m10 = masks_in[base + ((size_t)y1i * IMG_W + x0 ) * MAX_GT];
        const float m11 = masks_in[base + ((size_t)y1i * IMG_W + x1i) * MAX_GT];

        const float ofy = __fsub_rn(1.0f, fy), ofx = __fsub_rn(1.0f, fx);
        const float t0 = __fmul_rn(__fmul_rn(m00, ofy), ofx);
        const float t1 = __fmul_rn(__fmul_rn(m01, ofy), fx);
        const float t2 = __fmul_rn(__fmul_rn(m10, fy),  ofx);
        const float t3 = __fmul_rn(__fmul_rn(m11, fy),  fx);
        const float val = __fadd_rn(__fadd_rn(__fadd_rn(t0, t1), t2), t3);
        dst[i] = rintf(val);   // jnp.round = half-to-even
    }
}

// ---------------------------------------------------------------------------
// Launch
// ---------------------------------------------------------------------------
extern "C" void kernel_launch(void* const* d_in, const int* in_sizes, int n_in,
                              void* d_out, int out_size) {
    const float* proposals = nullptr;
    const int*   cls       = nullptr;
    const float* gtb       = nullptr;
    const float* masks     = nullptr;
    const float* std4      = nullptr;
    for (int i = 0; i < n_in; ++i) {
        switch (in_sizes[i]) {
            case BATCH * N_PROP * 4:               proposals = (const float*)d_in[i]; break;
            case BATCH * MAX_GT:                   cls       = (const int*)  d_in[i]; break;
            case BATCH * MAX_GT * 4:               gtb       = (const float*)d_in[i]; break;
            case BATCH * IMG_H * IMG_W * MAX_GT:   masks     = (const float*)d_in[i]; break;
            case 4:                                std4      = (const float*)d_in[i]; break;
            default: break;
        }
    }

    // derive per-image kp/kn on host (pure function of seed 42)
    KeySet ks;
    for (int b = 0; b < BATCH; ++b) {
        unsigned kb0, kb1;
        tf2x32(0u, 42u, 0u, (unsigned)b, kb0, kb1);          // split(key(42),16)[b]
        tf2x32(kb0, kb1, 0u, 0u, ks.kp0[b], ks.kp1[b]);      // split(key)[0]
        tf2x32(kb0, kb1, 0u, 1u, ks.kn0[b], ks.kn1[b]);      // split(key)[1]
    }

    float* out = (float*)d_out;
    k_score<<<dim3(N_PAD / 256, BATCH), 256>>>(proposals, cls, gtb, ks);
    k_select<<<BATCH, 1024>>>(proposals, cls, gtb, std4, out);
    k_mask<<<dim3(T_ROIS, BATCH), 256>>>(masks, out);
}

// round 8
// speedup vs baseline: 1.5760x; 1.5760x over previous
#include <cuda_runtime.h>
#include <cuda_bf16.h>
#include <stdint.h>

// ---------------------------------------------------------------------------
// Problem constants
// ---------------------------------------------------------------------------
#define BATCH     16
#define N_PROP    2000
#define N_PAD     2048
#define MAX_GT    100
#define IMG_H     160
#define IMG_W     160
#define T_ROIS    200
#define NUM_POS   66
#define NUM_NEG   134
#define MH        28
#define MW        28

// output layout (float32, tuple order: rois, class_ids, deltas, masks)
#define OFF_ROIS  0
#define OFF_CLS   (BATCH * T_ROIS * 4)                 // 12800
#define OFF_DEL   (OFF_CLS + BATCH * T_ROIS)           // 16000
#define OFF_MASK  (OFF_DEL + BATCH * T_ROIS * 4)       // 28800

// XLA rewrites x / const -> x * (1/const); replicate for bit-exactness.
#define RECIP_033  (1.0f / 0.33f)
#define RECIP_27   (1.0f / 27.0f)

// ---------------------------------------------------------------------------
// Scratch (__device__ globals; no allocations allowed)
// ---------------------------------------------------------------------------
__device__ unsigned long long g_poskey[BATCH * N_PROP];
__device__ unsigned long long g_negkey[BATCH * N_PROP];
__device__ unsigned long long g_ptop[BATCH][NUM_POS];
__device__ unsigned long long g_ntop[BATCH][NUM_NEG];
__device__ int   g_pg[BATCH][NUM_POS];
__device__ int   g_P[BATCH];
__device__ float g_mbox[BATCH * NUM_POS * 4];
__device__ int   g_mg[BATCH * NUM_POS];
__device__ int   g_mv[BATCH * NUM_POS];

// ---------------------------------------------------------------------------
// JAX threefry2x32 (partitionable mode semantics)
// ---------------------------------------------------------------------------
__host__ __device__ __forceinline__ void tf2x32(unsigned k0, unsigned k1,
                                                unsigned x0, unsigned x1,
                                                unsigned &o0, unsigned &o1) {
    unsigned ks0 = k0, ks1 = k1, ks2 = k0 ^ k1 ^ 0x1BD11BDAu;
    x0 += ks0; x1 += ks1;
#define TFR(r) { x0 += x1; x1 = (x1 << (r)) | (x1 >> (32 - (r))); x1 ^= x0; }
    TFR(13) TFR(15) TFR(26) TFR(6)  x0 += ks1; x1 += ks2 + 1u;
    TFR(17) TFR(29) TFR(16) TFR(24) x0 += ks2; x1 += ks0 + 2u;
    TFR(13) TFR(15) TFR(26) TFR(6)  x0 += ks0; x1 += ks1 + 3u;
    TFR(17) TFR(29) TFR(16) TFR(24) x0 += ks1; x1 += ks2 + 4u;
    TFR(13) TFR(15) TFR(26) TFR(6)  x0 += ks2; x1 += ks0 + 5u;
#undef TFR
    o0 = x0; o1 = x1;
}

__device__ __forceinline__ float u01_from_bits(unsigned bits) {
    return __uint_as_float((bits >> 9) | 0x3f800000u) - 1.0f;
}

// order-preserving float->u32 + ~idx tiebreak (stable top_k when sorted desc)
__device__ __forceinline__ unsigned long long pack_key(float f, int idx) {
    unsigned u = __float_as_uint(f);
    u = (u & 0x80000000u) ? ~u : (u | 0x80000000u);
    return (((unsigned long long)u) << 32) | (unsigned)(~idx);
}

struct KeySet {
    unsigned kp0[BATCH], kp1[BATCH], kn0[BATCH], kn1[BATCH];
};

// ---------------------------------------------------------------------------
// Kernel 1: pos/neg classification (division-free, exact) + sort keys.
// 4 threads per proposal, each covering 25 GTs.
//
// fl(inter/union) >= 0.5  <=>  2*inter >= union
//                          ||  (union - 2*inter) <= union * 2^-25
// (exact: 2*inter and union*2^-25 are power-of-2 scalings; in the band where
//  the second test decides, Sterbenz makes union - 2*inter exact.)
// ---------------------------------------------------------------------------
__global__ void __launch_bounds__(256)
k_score(const float4* __restrict__ proposals,
        const int*    __restrict__ gt_cls,
        const float4* __restrict__ gt_boxes,
        KeySet keys) {
    const int b = blockIdx.y;
    const int t = threadIdx.x;

    __shared__ float4 sg[MAX_GT];
    __shared__ float  sa[MAX_GT];
    __shared__ int    sv[MAX_GT];
    for (int i = t; i < MAX_GT; i += 256) {
        const float4 q = gt_boxes[b * MAX_GT + i];
        sg[i] = q;
        sa[i] = __fmul_rn(__fsub_rn(q.z, q.x), __fsub_rn(q.w, q.y));
        sv[i] = gt_cls[b * MAX_GT + i] > 0;
    }
    __syncthreads();

    const int n = blockIdx.x * 64 + (t >> 2);   // 64 proposals per block
    const int r = t & 3;
    if (n >= N_PROP) return;                    // whole-warp exits only

    const float4 p = proposals[b * N_PROP + n];
    const bool vp = (p.x != 0.f) || (p.y != 0.f) || (p.z != 0.f) || (p.w != 0.f);
    const float a1 = __fmul_rn(__fsub_rn(p.z, p.x), __fsub_rn(p.w, p.y));

    bool mypos = false;
    const int g0 = r * 25;
    #pragma unroll 5
    for (int k = 0; k < 25; ++k) {
        const int g = g0 + k;
        if (!sv[g]) continue;
        const float4 q = sg[g];
        const float ih = fmaxf(__fsub_rn(fminf(p.z, q.z), fmaxf(p.x, q.x)), 0.f);
        const float iw = fmaxf(__fsub_rn(fminf(p.w, q.w), fmaxf(p.y, q.y)), 0.f);
        const float inter = __fmul_rn(ih, iw);
        const float u = fmaxf(__fsub_rn(__fadd_rn(a1, sa[g]), inter), 1e-10f);
        const float t2 = __fmul_rn(2.0f, inter);           // exact
        mypos |= (t2 >= u) ||
                 (__fsub_rn(u, t2) <= __fmul_rn(u, 0x1p-25f));
    }

    const unsigned bal = __ballot_sync(0xFFFFFFFFu, mypos);
    const bool pos = ((bal >> ((t & 31) & ~3)) & 0xFu) != 0;   // quad any()

    unsigned o0, o1;
    if (r == 0) {
        tf2x32(keys.kp0[b], keys.kp1[b], 0u, (unsigned)n, o0, o1);
        g_poskey[b * N_PROP + n] =
            pack_key((pos && vp) ? u01_from_bits(o0 ^ o1) : -1.0f, n);
    } else if (r == 1) {
        tf2x32(keys.kn0[b], keys.kn1[b], 0u, (unsigned)n, o0, o1);
        g_negkey[b * N_PROP + n] =
            pack_key((!pos && vp) ? u01_from_bits(o0 ^ o1) : -1.0f, n);
    }
}

// ---------------------------------------------------------------------------
// Bitonic sort (descending), 2048 elements, 1024 threads
// ---------------------------------------------------------------------------
__device__ __forceinline__ void bitonic_desc(unsigned long long* s, int tid) {
    for (unsigned k = 2; k <= N_PAD; k <<= 1) {
        for (unsigned j = k >> 1; j > 0; j >>= 1) {
            __syncthreads();
            for (unsigned i = tid; i < N_PAD; i += 1024) {
                const unsigned ixj = i ^ j;
                if (ixj > i) {
                    const unsigned long long a = s[i], c = s[ixj];
                    const bool swp = ((i & k) == 0) ? (a < c) : (a > c);
                    if (swp) { s[i] = c; s[ixj] = a; }
                }
            }
        }
    }
    __syncthreads();
}

// ---------------------------------------------------------------------------
// Kernel 2: 32 blocks = (image, list). Sort keys; pos blocks also compute
// P and the per-positive GT argmax (warp per positive, lane covers 4 GTs;
// this is the ONLY place the rounded f32 divisions are reproduced).
// ---------------------------------------------------------------------------
__global__ void __launch_bounds__(1024)
k_sort(const float4* __restrict__ proposals,
       const int*    __restrict__ gt_cls,
       const float4* __restrict__ gt_boxes) {
    const int b    = blockIdx.x >> 1;
    const int list = blockIdx.x & 1;
    const int tid  = threadIdx.x;

    __shared__ unsigned long long s[N_PAD];
    const unsigned long long* src = list ? g_negkey : g_poskey;
    for (int i = tid; i < N_PAD; i += 1024)
        s[i] = (i < N_PROP) ? src[b * N_PROP + i] : 0ull;
    bitonic_desc(s, tid);

    if (list) {
        if (tid < NUM_NEG) g_ntop[b][tid] = s[tid];
        return;
    }

    if (tid < NUM_POS) g_ptop[b][tid] = s[tid];
    if (tid == 0) {
        int P = 0;
        for (int i = 0; i < NUM_POS; ++i)
            P += (((unsigned)(s[i] >> 32)) > 0x80000000u);
        g_P[b] = P;
    }

    // warp-per-positive argmax over where(valid, fl(inter/union), -1)
    const int wid = tid >> 5, lane = tid & 31;
    for (int slot = wid; slot < NUM_POS; slot += 32) {
        const int n = (int)(~(unsigned)s[slot]);
        const float4 p = proposals[b * N_PROP + n];
        const float a1 = __fmul_rn(__fsub_rn(p.z, p.x), __fsub_rn(p.w, p.y));

        float bestv = -2.0f; int bestg = 0;
        #pragma unroll 4
        for (int k = 0; k < 4; ++k) {
            const int g = lane + k * 32;
            if (g < MAX_GT) {
                float v = -1.0f;
                if (gt_cls[b * MAX_GT + g] > 0) {
                    const float4 q = gt_boxes[b * MAX_GT + g];
                    const float ih = fmaxf(__fsub_rn(fminf(p.z, q.z), fmaxf(p.x, q.x)), 0.f);
                    const float iw = fmaxf(__fsub_rn(fminf(p.w, q.w), fmaxf(p.y, q.y)), 0.f);
                    const float inter = __fmul_rn(ih, iw);
                    const float a2 = __fmul_rn(__fsub_rn(q.z, q.x), __fsub_rn(q.w, q.y));
                    const float u = fmaxf(__fsub_rn(__fadd_rn(a1, a2), inter), 1e-10f);
                    v = __fdiv_rn(inter, u);
                }
                if (v > bestv) { bestv = v; bestg = g; }   // ascending g: first-max
            }
        }
        #pragma unroll
        for (int off = 16; off; off >>= 1) {
            const float ov = __shfl_down_sync(0xFFFFFFFFu, bestv, off);
            const int   og = __shfl_down_sync(0xFFFFFFFFu, bestg, off);
            if (ov > bestv || (ov == bestv && og < bestg)) { bestv = ov; bestg = og; }
        }
        if (lane == 0) g_pg[b][slot] = bestg;
    }
}

// ---------------------------------------------------------------------------
// Kernel 3: emit rois / class_ids / deltas + mask metadata
// ---------------------------------------------------------------------------
__global__ void __launch_bounds__(256)
k_emit(const float4* __restrict__ proposals,
       const int*    __restrict__ gt_cls,
       const float4* __restrict__ gt_boxes,
       const float*  __restrict__ std4,
       float* __restrict__ out) {
    const int b = blockIdx.x;
    const int tid = threadIdx.x;

    float* o_rois = out + OFF_ROIS;
    float* o_cls  = out + OFF_CLS;
    float* o_del  = out + OFF_DEL;

    if (tid < NUM_POS) {
        const unsigned long long key = g_ptop[b][tid];
        const int n = (int)(~(unsigned)key);
        const int v = ((unsigned)(key >> 32)) > 0x80000000u;
        const int g = g_pg[b][tid];
        const float vf = v ? 1.0f : 0.0f;

        const float4 p = proposals[b * N_PROP + n];
        const float b0 = p.x, b1 = p.y, b2 = p.z, b3 = p.w;

        float q0, q1, q2, q3;
        if (v) {
            const float4 q = gt_boxes[b * MAX_GT + g];
            q0 = q.x; q1 = q.y; q2 = q.z; q3 = q.w;
        } else {
            q0 = b0; q1 = b1; q2 = b2; q3 = b3;
        }

        const float h  = __fsub_rn(b2, b0), w  = __fsub_rn(b3, b1);
        const float cy = __fadd_rn(b0, __fmul_rn(0.5f, h));
        const float cx = __fadd_rn(b1, __fmul_rn(0.5f, w));
        const float gh = __fsub_rn(q2, q0), gw = __fsub_rn(q3, q1);
        const float gcy = __fadd_rn(q0, __fmul_rn(0.5f, gh));
        const float gcx = __fadd_rn(q1, __fmul_rn(0.5f, gw));

        float d0 = __fdiv_rn(__fsub_rn(gcy, cy), h);
        float d1 = __fdiv_rn(__fsub_rn(gcx, cx), w);
        float d2 = logf(__fdiv_rn(gh, h));
        float d3 = logf(__fdiv_rn(gw, w));
        d0 = __fmul_rn(__fdiv_rn(d0, std4[0]), vf);
        d1 = __fmul_rn(__fdiv_rn(d1, std4[1]), vf);
        d2 = __fmul_rn(__fdiv_rn(d2, std4[2]), vf);
        d3 = __fmul_rn(__fdiv_rn(d3, std4[3]), vf);

        float* rr = o_rois + (b * T_ROIS + tid) * 4;
        rr[0] = __fmul_rn(b0, vf); rr[1] = __fmul_rn(b1, vf);
        rr[2] = __fmul_rn(b2, vf); rr[3] = __fmul_rn(b3, vf);

        o_cls[b * T_ROIS + tid] = v ? (float)gt_cls[b * MAX_GT + g] : 0.0f;

        float* dd = o_del + (b * T_ROIS + tid) * 4;
        dd[0] = d0; dd[1] = d1; dd[2] = d2; dd[3] = d3;

        const int mi = b * NUM_POS + tid;
        g_mbox[mi * 4 + 0] = b0; g_mbox[mi * 4 + 1] = b1;
        g_mbox[mi * 4 + 2] = b2; g_mbox[mi * 4 + 3] = b3;
        g_mg[mi] = g;
        g_mv[mi] = v;
    } else if (tid < T_ROIS) {
        const int j = tid - NUM_POS;
        const int P = g_P[b];
        const int tP = (int)__fmul_rn((float)P, RECIP_033);  // XLA recip-mul
        int need = tP - P;
        need = need < 0 ? 0 : (need > NUM_NEG ? NUM_NEG : need);

        const unsigned long long key = g_ntop[b][j];
        const int n = (int)(~(unsigned)key);
        const int v = (((unsigned)(key >> 32)) > 0x80000000u) && (j < need);
        const float vf = v ? 1.0f : 0.0f;
        const float4 p = proposals[b * N_PROP + n];

        float* rr = o_rois + (b * T_ROIS + tid) * 4;
        rr[0] = __fmul_rn(p.x, vf); rr[1] = __fmul_rn(p.y, vf);
        rr[2] = __fmul_rn(p.z, vf); rr[3] = __fmul_rn(p.w, vf);
        o_cls[b * T_ROIS + tid] = 0.0f;
        float* dd = o_del + (b * T_ROIS + tid) * 4;
        dd[0] = 0.f; dd[1] = 0.f; dd[2] = 0.f; dd[3] = 0.f;
    }
}

// ---------------------------------------------------------------------------
// Kernel 4: mask crop_and_resize (tf bilinear) — one thread per pixel
// ---------------------------------------------------------------------------
__global__ void __launch_bounds__(MH * MW)
k_mask(const float* __restrict__ masks_in,
       float* __restrict__ out) {
    const int slot = blockIdx.x;
    const int b    = blockIdx.y;
    float* dst = out + OFF_MASK + (size_t)(b * T_ROIS + slot) * (MH * MW);
    const int i = threadIdx.x;

    int v = 0, g = 0;
    float y1 = 0.f, x1 = 0.f, y2 = 0.f, x2 = 0.f;
    if (slot < NUM_POS) {
        const int mi = b * NUM_POS + slot;
        v = g_mv[mi];
        g = g_mg[mi];
        y1 = g_mbox[mi * 4 + 0]; x1 = g_mbox[mi * 4 + 1];
        y2 = g_mbox[mi * 4 + 2]; x2 = g_mbox[mi * 4 + 3];
    }
    if (!v) { dst[i] = 0.0f; return; }

    const size_t base = (size_t)b * IMG_H * IMG_W * MAX_GT + g;
    const float dy = __fsub_rn(y2, y1);
    const float dx = __fsub_rn(x2, x1);

    const int r = i / MW, c = i % MW;
    const float ty = __fmul_rn((float)r, RECIP_27);   // XLA recip-mul
    const float tx = __fmul_rn((float)c, RECIP_27);
    const float ys = __fmul_rn(__fadd_rn(y1, __fmul_rn(ty, dy)), (float)(IMG_H - 1));
    const float xs = __fmul_rn(__fadd_rn(x1, __fmul_rn(tx, dx)), (float)(IMG_W - 1));
    const float y0f = floorf(ys), x0f = floorf(xs);
    const float fy = __fsub_rn(ys, y0f), fx = __fsub_rn(xs, x0f);
    int y0 = (int)y0f; y0 = y0 < 0 ? 0 : (y0 > IMG_H - 1 ? IMG_H - 1 : y0);
    int x0 = (int)x0f; x0 = x0 < 0 ? 0 : (x0 > IMG_W - 1 ? IMG_W - 1 : x0);
    const int y1i = min(y0 + 1, IMG_H - 1);
    const int x1i = min(x0 + 1, IMG_W - 1);

    const float m00 = masks_in[base + ((size_t)y0  * IMG_W + x0 ) * MAX_GT];
    const float m01 = masks_in[base + ((size_t)y0  * IMG_W + x1i) * MAX_GT];
    const float m10 = masks_in[base + ((size_t)y1i * IMG_W + x0 ) * MAX_GT];
    const float m11 = masks_in[base + ((size_t)y1i * IMG_W + x1i) * MAX_GT];

    const float ofy = __fsub_rn(1.0f, fy), ofx = __fsub_rn(1.0f, fx);
    const float t0 = __fmul_rn(__fmul_rn(m00, ofy), ofx);
    const float t1 = __fmul_rn(__fmul_rn(m01, ofy), fx);
    const float t2 = __fmul_rn(__fmul_rn(m10, fy),  ofx);
    const float t3 = __fmul_rn(__fmul_rn(m11, fy),  fx);
    const float val = __fadd_rn(__fadd_rn(__fadd_rn(t0, t1), t2), t3);
    dst[i] = rintf(val);   // jnp.round = half-to-even
}

// ---------------------------------------------------------------------------
// Launch
// ---------------------------------------------------------------------------
extern "C" void kernel_launch(void* const* d_in, const int* in_sizes, int n_in,
                              void* d_out, int out_size) {
    const float* proposals = nullptr;
    const int*   cls       = nullptr;
    const float* gtb       = nullptr;
    const float* masks     = nullptr;
    const float* std4      = nullptr;
    for (int i = 0; i < n_in; ++i) {
        switch (in_sizes[i]) {
            case BATCH * N_PROP * 4:               proposals = (const float*)d_in[i]; break;
            case BATCH * MAX_GT:                   cls       = (const int*)  d_in[i]; break;
            case BATCH * MAX_GT * 4:               gtb       = (const float*)d_in[i]; break;
            case BATCH * IMG_H * IMG_W * MAX_GT:   masks     = (const float*)d_in[i]; break;
            case 4:                                std4      = (const float*)d_in[i]; break;
            default: break;
        }
    }

    // per-image kp/kn (pure function of seed 42)
    KeySet ks;
    for (int b = 0; b < BATCH; ++b) {
        unsigned kb0, kb1;
        tf2x32(0u, 42u, 0u, (unsigned)b, kb0, kb1);          // split(key(42),16)[b]
        tf2x32(kb0, kb1, 0u, 0u, ks.kp0[b], ks.kp1[b]);      // split(key)[0]
        tf2x32(kb0, kb1, 0u, 1u, ks.kn0[b], ks.kn1[b]);      // split(key)[1]
    }

    const float4* prop4 = (const float4*)proposals;
    const float4* gtb4  = (const float4*)gtb;
    float* out = (float*)d_out;

    k_score<<<dim3(32, BATCH), 256>>>(prop4, cls, gtb4, ks);
    k_sort<<<2 * BATCH, 1024>>>(prop4, cls, gtb4);
    k_emit<<<BATCH, 256>>>(prop4, cls, gtb4, std4, out);
    k_mask<<<dim3(T_ROIS, BATCH), MH * MW>>>(masks, out);
}